// round 12
// baseline (speedup 1.0000x reference)
#include <cuda_runtime.h>
#include <cuda_bf16.h>
#include <cuda_fp16.h>
#include <cstdint>

#define Bn 8
#define Cn 512
#define Sn 1024
#define NH 8
#define NG 32
#define EPSV 1e-5f

// ---------------------------------------------------------------------------
// Static device scratch (allocation-free rule)
// ---------------------------------------------------------------------------
__device__ float  g_xnT[(long)Bn * Sn * Cn];            // (b, s, c) fp32
__device__ __half g_qh[(long)Bn * NH * Sn * 64];        // (bh, t, d) hi
__device__ __half g_ql[(long)Bn * NH * Sn * 64];        // lo
__device__ __half g_kh[(long)Bn * NH * Sn * 64];        // (bh, s, d)
__device__ __half g_kl[(long)Bn * NH * Sn * 64];
__device__ __half g_vh[(long)Bn * NH * 64 * Sn];        // (bh, d, s)
__device__ __half g_vl[(long)Bn * NH * 64 * Sn];
__device__ float  g_hT[(long)Bn * Sn * Cn];             // (b, t, c) fp32
__device__ float  g_mean[Bn * NG];
__device__ float  g_rstd[Bn * NG];

// ---------------------------------------------------------------------------
// PTX helpers (base ISA only)
// ---------------------------------------------------------------------------
__device__ __forceinline__ uint32_t smem_u32(const void* p) {
    uint32_t a;
    asm("{ .reg .u64 t; cvta.to.shared.u64 t, %1; cvt.u32.u64 %0, t; }" : "=r"(a) : "l"(p));
    return a;
}
__device__ __forceinline__ void ldsm4(uint32_t* r, uint32_t addr) {
    asm volatile("ldmatrix.sync.aligned.m8n8.x4.shared.b16 {%0,%1,%2,%3}, [%4];"
        : "=r"(r[0]), "=r"(r[1]), "=r"(r[2]), "=r"(r[3]) : "r"(addr));
}
__device__ __forceinline__ void mma16816(float* c, const uint32_t* a, const uint32_t* b) {
    asm volatile("mma.sync.aligned.m16n8k16.row.col.f32.f16.f16.f32 "
        "{%0,%1,%2,%3}, {%4,%5,%6,%7}, {%8,%9}, {%0,%1,%2,%3};"
        : "+f"(c[0]), "+f"(c[1]), "+f"(c[2]), "+f"(c[3])
        : "r"(a[0]), "r"(a[1]), "r"(a[2]), "r"(a[3]), "r"(b[0]), "r"(b[1]));
}
__device__ __forceinline__ uint32_t packh2(float a, float b) {
    __half2 t = __floats2half2_rn(a, b);
    return *reinterpret_cast<uint32_t*>(&t);
}
#define SWZ(o)    ((o) ^ (((o) >> 3) & 0x70))
#define CP16(d, s)   asm volatile("cp.async.cg.shared.global [%0], [%1], 16;" :: "r"(d), "l"(s) : "memory")
#define CP_COMMIT()  asm volatile("cp.async.commit_group;" ::: "memory")
#define CP_WAIT0()   asm volatile("cp.async.wait_group 0;" ::: "memory")
#define CP_WAIT1()   asm volatile("cp.async.wait_group 1;" ::: "memory")

__device__ __forceinline__ void split_h(float v, __half& h, __half& l) {
    h = __float2half_rn(v);
    l = __float2half_rn(v - __half2float(h));
}

// ---------------------------------------------------------------------------
// HMMA GEMM (fp16x3): D[m,n] = sum_k A[m,k]*B[n,k], both K-major fp32.
// cp.async double-buffered fp32 staging -> in-smem convert -> term-major MMA.
// MODE 0: QKV -> scatter into half hi/lo q/k/v tensors (+bias), z=b
// MODE 3: proj (+bias +residual) -> out fp32, z=b
// ---------------------------------------------------------------------------
template<int BM, int BN, int MODE>
__global__ __launch_bounds__(256)
void mma_gemm(const float* __restrict__ A, long ldA, long Az,
              const float* __restrict__ Bp, long ldB, long Bz,
              int K, const float* __restrict__ bias, const float* __restrict__ resid,
              float* __restrict__ OutF,
              __half* __restrict__ H0, __half* __restrict__ H1,
              __half* __restrict__ H2, __half* __restrict__ H3,
              __half* __restrict__ H4, __half* __restrict__ H5)
{
    extern __shared__ char smraw[];
    uint32_t sb = smem_u32(smraw);
    uint32_t aB = (sb + 1023u) & ~1023u;
    char* const delta = smraw + (aB - sb);   // delta + (off-aB) = host ptr for smem off
    auto sp = [&](uint32_t off) -> char* { return delta + (off - aB); };

    // half tiles (64 KB)
    uint32_t aHiU = aB, aLoU = aB + BM * 128;
    uint32_t bHiU = aB + 2 * BM * 128, bLoU = bHiU + BN * 128;
    // fp32 staging: rows of 64 floats padded to 272 B; A then B per stage
    constexpr uint32_t AST = BM * 272u;           // 34816
    constexpr uint32_t BST = BN * 272u;
    constexpr uint32_t STG2 = AST + BST;          // one stage
    uint32_t f32b = aB + (uint32_t)(2 * BM * 128 + 2 * BN * 128);
    float* stage = (float*)sp(aB);                // epilogue overlay

    int tid = threadIdx.x, wid = tid >> 5, lane = tid & 31;
    int wm = wid >> 2, wn = wid & 3;
    int m0 = blockIdx.y * BM, n0 = blockIdx.x * BN, z = blockIdx.z;
    const float* Ab = A  + (long)z * Az;
    const float* Bb = Bp + (long)z * Bz;

    float acc[4][4][4];
    #pragma unroll
    for (int mi = 0; mi < 4; mi++)
        #pragma unroll
        for (int ni = 0; ni < 4; ni++)
            #pragma unroll
            for (int j = 0; j < 4; j++) acc[mi][ni][j] = 0.f;

    auto cp_load = [&](int pass, int s) {
        int k0 = pass << 6;
        uint32_t stA = f32b + (uint32_t)s * STG2;
        uint32_t stB = stA + AST;
        #pragma unroll
        for (int i = 0; i < BM / 16; i++) {
            int id = tid + i * 256;
            int row = id >> 4, c = id & 15;
            CP16(stA + (uint32_t)row * 272u + (uint32_t)c * 16u,
                 Ab + (long)(m0 + row) * ldA + k0 + c * 4);
        }
        #pragma unroll
        for (int i = 0; i < BN / 16; i++) {
            int id = tid + i * 256;
            int row = id >> 4, c = id & 15;
            CP16(stB + (uint32_t)row * 272u + (uint32_t)c * 16u,
                 Bb + (long)(n0 + row) * ldB + k0 + c * 4);
        }
        CP_COMMIT();
    };

    auto convert = [&](int s) {
        uint32_t stA = f32b + (uint32_t)s * STG2;
        uint32_t stB = stA + AST;
        #pragma unroll
        for (int i = 0; i < BM / 16; i++) {
            int id = tid + i * 256;
            int row = id >> 4, c = id & 15;
            float4 v = *(const float4*)sp(stA + (uint32_t)row * 272u + (uint32_t)c * 16u);
            __half2 h0 = __floats2half2_rn(v.x, v.y), h1 = __floats2half2_rn(v.z, v.w);
            float2 f0 = __half22float2(h0), f1 = __half22float2(h1);
            uint2 hi = make_uint2(*(uint32_t*)&h0, *(uint32_t*)&h1);
            uint2 lo = make_uint2(packh2(v.x - f0.x, v.y - f0.y),
                                  packh2(v.z - f1.x, v.w - f1.y));
            uint32_t sw = SWZ((uint32_t)row * 128u + (uint32_t)c * 8u);
            *(uint2*)sp(aHiU + sw) = hi;
            *(uint2*)sp(aLoU + sw) = lo;
        }
        #pragma unroll
        for (int i = 0; i < BN / 16; i++) {
            int id = tid + i * 256;
            int row = id >> 4, c = id & 15;
            float4 v = *(const float4*)sp(stB + (uint32_t)row * 272u + (uint32_t)c * 16u);
            __half2 h0 = __floats2half2_rn(v.x, v.y), h1 = __floats2half2_rn(v.z, v.w);
            float2 f0 = __half22float2(h0), f1 = __half22float2(h1);
            uint2 hi = make_uint2(*(uint32_t*)&h0, *(uint32_t*)&h1);
            uint2 lo = make_uint2(packh2(v.x - f0.x, v.y - f0.y),
                                  packh2(v.z - f1.x, v.w - f1.y));
            uint32_t sw = SWZ((uint32_t)row * 128u + (uint32_t)c * 8u);
            *(uint2*)sp(bHiU + sw) = hi;
            *(uint2*)sp(bLoU + sw) = lo;
        }
    };

    int nPass = K >> 6;
    cp_load(0, 0);
    for (int pass = 0; pass < nPass; ++pass) {
        if (pass + 1 < nPass) { cp_load(pass + 1, (pass + 1) & 1); CP_WAIT1(); }
        else CP_WAIT0();
        __syncthreads();                 // stage (pass&1) visible to all
        convert(pass & 1);
        __syncthreads();                 // half tiles ready

        #pragma unroll
        for (int kc = 0; kc < 4; kc++) {
            uint32_t ah[4][4], al[4][4], bhf[4][2], blf[4][2];
            #pragma unroll
            for (int mi = 0; mi < 4; mi++) {
                int row = wm * 64 + mi * 16 + (lane & 15);
                uint32_t sw = SWZ((uint32_t)row * 128u + kc * 32u + ((lane >> 4) << 4));
                ldsm4(ah[mi], aHiU + sw);
                ldsm4(al[mi], aLoU + sw);
            }
            #pragma unroll
            for (int g = 0; g < 2; g++) {
                int nr = wn * 32 + g * 16 + (lane & 7) + ((lane >> 4) & 1) * 8;
                uint32_t sw = SWZ((uint32_t)nr * 128u + kc * 32u + (((lane >> 3) & 1) << 4));
                uint32_t t4[4];
                ldsm4(t4, bHiU + sw);
                bhf[g*2][0] = t4[0]; bhf[g*2][1] = t4[1];
                bhf[g*2+1][0] = t4[2]; bhf[g*2+1][1] = t4[3];
                ldsm4(t4, bLoU + sw);
                blf[g*2][0] = t4[0]; blf[g*2][1] = t4[1];
                blf[g*2+1][0] = t4[2]; blf[g*2+1][1] = t4[3];
            }
            // term-major: 16 independent MMAs per group (RAW distance 16)
            #pragma unroll
            for (int mi = 0; mi < 4; mi++)
                #pragma unroll
                for (int ni = 0; ni < 4; ni++)
                    mma16816(acc[mi][ni], ah[mi], bhf[ni]);
            #pragma unroll
            for (int mi = 0; mi < 4; mi++)
                #pragma unroll
                for (int ni = 0; ni < 4; ni++)
                    mma16816(acc[mi][ni], al[mi], bhf[ni]);
            #pragma unroll
            for (int mi = 0; mi < 4; mi++)
                #pragma unroll
                for (int ni = 0; ni < 4; ni++)
                    mma16816(acc[mi][ni], ah[mi], blf[ni]);
        }
        __syncthreads();                 // protect half tiles before next convert
    }

    constexpr int SLD = BN + 2;
    #pragma unroll
    for (int mi = 0; mi < 4; mi++)
        #pragma unroll
        for (int ni = 0; ni < 4; ni++) {
            int r = wm * 64 + mi * 16 + (lane >> 2);
            int c = wn * 32 + ni * 8 + (lane & 3) * 2;
            *(float2*)&stage[r * SLD + c] = make_float2(acc[mi][ni][0], acc[mi][ni][1]);
            *(float2*)&stage[(r + 8) * SLD + c] = make_float2(acc[mi][ni][2], acc[mi][ni][3]);
        }
    __syncthreads();

    if (MODE == 0) {
        int three = m0 >> 9;
        int b = z;
        if (three < 2) {
            __half* dh = three ? H2 : H0;
            __half* dl = three ? H3 : H1;
            for (int cc = wid; cc < BN; cc += 8) {
                int t = n0 + cc;
                #pragma unroll
                for (int ii = 0; ii < BM / 32; ii++) {
                    int r = lane + 32 * ii;
                    int o = (m0 + r) & 511;
                    int h = o >> 6, d = o & 63;
                    float val = stage[r * SLD + cc] + bias[m0 + r];
                    __half hi, lo; split_h(val, hi, lo);
                    long idx = (((long)(b * 8 + h) << 10) + t) * 64 + d;
                    dh[idx] = hi; dl[idx] = lo;
                }
            }
        } else {
            for (int r = wid; r < BM; r += 8) {
                int o = (m0 + r) & 511;
                int h = o >> 6, d = o & 63;
                float bv = bias[m0 + r];
                long basei = ((long)(b * 8 + h) * 64 + d) * 1024 + n0;
                #pragma unroll
                for (int j = 0; j < BN / 32; j++) {
                    int c = lane + 32 * j;
                    float val = stage[r * SLD + c] + bv;
                    __half hi, lo; split_h(val, hi, lo);
                    H4[basei + c] = hi; H5[basei + c] = lo;
                }
            }
        }
    } else {
        for (int r = wid; r < BM; r += 8) {
            int o = m0 + r;
            float bv = bias[o];
            long basei = (long)z * 524288 + (long)o * 1024 + n0;
            #pragma unroll
            for (int j = 0; j < BN / 32; j++) {
                int c = lane + 32 * j;
                OutF[basei + c] = stage[r * SLD + c] + bv + resid[basei + c];
            }
        }
    }
}

// ---------------------------------------------------------------------------
// Fused flash attention: 128-thread CTAs (4 warps), 64 Q rows per CTA,
// SK=64 keys/stage, double-buffered, 2 CTAs/SM, term-major MMA ordering.
// SMEM: Q hi 0..8K, Q lo 8K..16K; stage s @16K + s*32K:
//       K hi +0, K lo +8K, V hi +16K, V lo +24K   (all 64x64 half tiles)
// ---------------------------------------------------------------------------
__global__ __launch_bounds__(128)
void attn_kernel(const __half* __restrict__ qh, const __half* __restrict__ ql,
                 const __half* __restrict__ kh, const __half* __restrict__ kl,
                 const __half* __restrict__ vh, const __half* __restrict__ vl,
                 float* __restrict__ hT)
{
    extern __shared__ char smraw[];
    uint32_t sb = smem_u32(smraw);
    uint32_t base = (sb + 1023u) & ~1023u;

    int tid = threadIdx.x, wid = tid >> 5, lane = tid & 31;
    int bh = blockIdx.y;
    int t0 = blockIdx.x * 64;
    int b = bh >> 3, h = bh & 7;

    // ---- prologue: Q hi/lo (64 rows) ----
    #pragma unroll
    for (int i = 0; i < 4; i++) {
        int id = tid + i * 128;
        int row = id >> 3, c = id & 7;
        uint32_t sw = SWZ((uint32_t)row * 128u + c * 16u);
        long off = ((long)bh * 1024 + t0 + row) * 64 + c * 8;
        CP16(base + sw,         qh + off);
        CP16(base + 8192u + sw, ql + off);
    }

    auto load_kv = [&](int it, int s) {
        uint32_t stg = base + 16384u + (uint32_t)s * 32768u;
        int s0 = it * 64;
        #pragma unroll
        for (int i = 0; i < 4; i++) {
            int id = tid + i * 128;
            int row = id >> 3, c = id & 7;
            uint32_t sw = SWZ((uint32_t)row * 128u + c * 16u);
            long koff = ((long)bh * 1024 + s0 + row) * 64 + c * 8;
            CP16(stg + sw,          kh + koff);
            CP16(stg + 8192u + sw,  kl + koff);
            long voff = ((long)bh * 64 + row) * 1024 + s0 + c * 8;
            CP16(stg + 16384u + sw, vh + voff);
            CP16(stg + 24576u + sw, vl + voff);
        }
        CP_COMMIT();
    };
    load_kv(0, 0);

    float m0v = -1e30f, m1v = -1e30f, l0 = 0.f, l1 = 0.f;
    float acc_o[8][4];
    #pragma unroll
    for (int ni = 0; ni < 8; ni++)
        #pragma unroll
        for (int j = 0; j < 4; j++) acc_o[ni][j] = 0.f;

    for (int it = 0; it < 16; it++) {
        if (it < 15) { load_kv(it + 1, (it + 1) & 1); CP_WAIT1(); }
        else CP_WAIT0();
        __syncthreads();
        uint32_t stg = base + 16384u + (uint32_t)(it & 1) * 32768u;

        // ---- S = Q K^T over 64 keys (fp16x3, term-major) ----
        float s_acc[8][4];
        #pragma unroll
        for (int ni = 0; ni < 8; ni++)
            #pragma unroll
            for (int j = 0; j < 4; j++) s_acc[ni][j] = 0.f;

        #pragma unroll
        for (int kc = 0; kc < 4; kc++) {
            uint32_t ah[4], al[4], th[4][4], tl[4][4];
            {
                int row = wid * 16 + (lane & 15);
                uint32_t sw = SWZ((uint32_t)row * 128u + kc * 32u + ((lane >> 4) << 4));
                ldsm4(ah, base + sw);
                ldsm4(al, base + 8192u + sw);
            }
            #pragma unroll
            for (int g = 0; g < 4; g++) {
                int nr = g * 16 + (lane & 7) + ((lane >> 4) & 1) * 8;
                uint32_t sw = SWZ((uint32_t)nr * 128u + kc * 32u + (((lane >> 3) & 1) << 4));
                ldsm4(th[g], stg + sw);
                ldsm4(tl[g], stg + 8192u + sw);
            }
            #pragma unroll
            for (int g = 0; g < 4; g++) {
                mma16816(s_acc[2*g],   ah, th[g]);
                mma16816(s_acc[2*g+1], ah, th[g] + 2);
            }
            #pragma unroll
            for (int g = 0; g < 4; g++) {
                mma16816(s_acc[2*g],   al, th[g]);
                mma16816(s_acc[2*g+1], al, th[g] + 2);
            }
            #pragma unroll
            for (int g = 0; g < 4; g++) {
                mma16816(s_acc[2*g],   ah, tl[g]);
                mma16816(s_acc[2*g+1], ah, tl[g] + 2);
            }
        }

        // ---- online softmax ----
        float mx0 = -1e30f, mx1 = -1e30f;
        #pragma unroll
        for (int ni = 0; ni < 8; ni++) {
            s_acc[ni][0] *= 0.125f; s_acc[ni][1] *= 0.125f;
            s_acc[ni][2] *= 0.125f; s_acc[ni][3] *= 0.125f;
            mx0 = fmaxf(mx0, fmaxf(s_acc[ni][0], s_acc[ni][1]));
            mx1 = fmaxf(mx1, fmaxf(s_acc[ni][2], s_acc[ni][3]));
        }
        mx0 = fmaxf(mx0, __shfl_xor_sync(0xffffffffu, mx0, 1));
        mx0 = fmaxf(mx0, __shfl_xor_sync(0xffffffffu, mx0, 2));
        mx1 = fmaxf(mx1, __shfl_xor_sync(0xffffffffu, mx1, 1));
        mx1 = fmaxf(mx1, __shfl_xor_sync(0xffffffffu, mx1, 2));
        float mn0 = fmaxf(m0v, mx0), mn1 = fmaxf(m1v, mx1);
        float cr0 = __expf(m0v - mn0), cr1 = __expf(m1v - mn1);
        m0v = mn0; m1v = mn1;
        float sm0 = 0.f, sm1 = 0.f;
        #pragma unroll
        for (int ni = 0; ni < 8; ni++) {
            s_acc[ni][0] = __expf(s_acc[ni][0] - m0v);
            s_acc[ni][1] = __expf(s_acc[ni][1] - m0v);
            s_acc[ni][2] = __expf(s_acc[ni][2] - m1v);
            s_acc[ni][3] = __expf(s_acc[ni][3] - m1v);
            sm0 += s_acc[ni][0] + s_acc[ni][1];
            sm1 += s_acc[ni][2] + s_acc[ni][3];
        }
        sm0 += __shfl_xor_sync(0xffffffffu, sm0, 1);
        sm0 += __shfl_xor_sync(0xffffffffu, sm0, 2);
        sm1 += __shfl_xor_sync(0xffffffffu, sm1, 1);
        sm1 += __shfl_xor_sync(0xffffffffu, sm1, 2);
        l0 = l0 * cr0 + sm0;
        l1 = l1 * cr1 + sm1;
        #pragma unroll
        for (int ni = 0; ni < 8; ni++) {
            acc_o[ni][0] *= cr0; acc_o[ni][1] *= cr0;
            acc_o[ni][2] *= cr1; acc_o[ni][3] *= cr1;
        }

        // ---- O += P V (fp16x3, term-major per kp) ----
        #pragma unroll
        for (int kp = 0; kp < 4; kp++) {
            uint32_t paf[4], plf[4];
            #pragma unroll
            for (int q2 = 0; q2 < 2; q2++) {
                int ni = 2 * kp + q2;
                __half2 hA = __floats2half2_rn(s_acc[ni][0], s_acc[ni][1]);
                __half2 hB = __floats2half2_rn(s_acc[ni][2], s_acc[ni][3]);
                float2 fA = __half22float2(hA), fB = __half22float2(hB);
                paf[2*q2]   = *reinterpret_cast<uint32_t*>(&hA);
                paf[2*q2+1] = *reinterpret_cast<uint32_t*>(&hB);
                plf[2*q2]   = packh2(s_acc[ni][0] - fA.x, s_acc[ni][1] - fA.y);
                plf[2*q2+1] = packh2(s_acc[ni][2] - fB.x, s_acc[ni][3] - fB.y);
            }
            uint32_t tv[4][4], tw[4][4];
            #pragma unroll
            for (int g2 = 0; g2 < 4; g2++) {
                int nr = g2 * 16 + (lane & 7) + ((lane >> 4) & 1) * 8;
                uint32_t sw = SWZ((uint32_t)nr * 128u + kp * 32u + (((lane >> 3) & 1) << 4));
                ldsm4(tv[g2], stg + 16384u + sw);
                ldsm4(tw[g2], stg + 24576u + sw);
            }
            #pragma unroll
            for (int g2 = 0; g2 < 4; g2++) {
                mma16816(acc_o[2*g2],   paf, tv[g2]);
                mma16816(acc_o[2*g2+1], paf, tv[g2] + 2);
            }
            #pragma unroll
            for (int g2 = 0; g2 < 4; g2++) {
                mma16816(acc_o[2*g2],   plf, tv[g2]);
                mma16816(acc_o[2*g2+1], plf, tv[g2] + 2);
            }
            #pragma unroll
            for (int g2 = 0; g2 < 4; g2++) {
                mma16816(acc_o[2*g2],   paf, tw[g2]);
                mma16816(acc_o[2*g2+1], paf, tw[g2] + 2);
            }
        }
        __syncthreads();
    }

    // ---- epilogue: hT[b, t, h*64+d] = O / l ----
    float inv0 = 1.f / l0, inv1 = 1.f / l1;
    int tr = t0 + wid * 16 + (lane >> 2);
    #pragma unroll
    for (int ni = 0; ni < 8; ni++) {
        int d0 = ni * 8 + (lane & 3) * 2;
        *(float2*)&hT[((long)b * 1024 + tr) * 512 + h * 64 + d0] =
            make_float2(acc_o[ni][0] * inv0, acc_o[ni][1] * inv0);
        *(float2*)&hT[((long)b * 1024 + tr + 8) * 512 + h * 64 + d0] =
            make_float2(acc_o[ni][2] * inv1, acc_o[ni][3] * inv1);
    }
}

// ---------------------------------------------------------------------------
// Reductions, GroupNorm
// ---------------------------------------------------------------------------
__device__ __forceinline__ float warp_sum(float v) {
    #pragma unroll
    for (int o = 16; o; o >>= 1) v += __shfl_xor_sync(0xffffffffu, v, o);
    return v;
}
__device__ __forceinline__ float block_sum(float v, float* sh) {
    int lane = threadIdx.x & 31, w = threadIdx.x >> 5, nw = blockDim.x >> 5;
    v = warp_sum(v);
    if (lane == 0) sh[w] = v;
    __syncthreads();
    if (w == 0) {
        float r = (lane < nw) ? sh[lane] : 0.f;
        r = warp_sum(r);
        if (lane == 0) sh[0] = r;
    }
    __syncthreads();
    float r = sh[0];
    __syncthreads();
    return r;
}

__global__ void gn_stats_kernel(const float* __restrict__ x) {
    __shared__ float sh[32];
    int bg = blockIdx.x;
    const float4* p = (const float4*)(x + (long)bg * 16384);
    float s = 0.f, s2 = 0.f;
    for (int i = threadIdx.x; i < 4096; i += blockDim.x) {
        float4 v = p[i];
        s  += v.x + v.y + v.z + v.w;
        s2 += v.x*v.x + v.y*v.y + v.z*v.z + v.w*v.w;
    }
    s  = block_sum(s,  sh);
    s2 = block_sum(s2, sh);
    if (threadIdx.x == 0) {
        float mu  = s * (1.f / 16384.f);
        float var = s2 * (1.f / 16384.f) - mu * mu;
        g_mean[bg] = mu;
        g_rstd[bg] = rsqrtf(var + EPSV);
    }
}

__global__ void gn_apply_T_kernel(const float* __restrict__ x,
                                  const float* __restrict__ gamma,
                                  const float* __restrict__ beta) {
    __shared__ float t[32][33];
    int b = blockIdx.z, c0 = blockIdx.y * 32, s0 = blockIdx.x * 32;
    for (int i = threadIdx.y; i < 32; i += 8) {
        int c = c0 + i;
        int bg = b * 32 + (c >> 4);
        float a = g_rstd[bg] * gamma[c];
        float bb = beta[c] - g_mean[bg] * a;
        t[i][threadIdx.x] = x[((long)b * 512 + c) * 1024 + s0 + threadIdx.x] * a + bb;
    }
    __syncthreads();
    for (int i = threadIdx.y; i < 32; i += 8)
        g_xnT[((long)b * 1024 + s0 + i) * 512 + c0 + threadIdx.x] = t[threadIdx.x][i];
}

// ---------------------------------------------------------------------------
// Launch
// ---------------------------------------------------------------------------
extern "C" void kernel_launch(void* const* d_in, const int* in_sizes, int n_in,
                              void* d_out, int out_size) {
    const float* x      = (const float*)d_in[0];
    const float* gamma  = (const float*)d_in[1];
    const float* beta   = (const float*)d_in[2];
    const float* w_qkv  = (const float*)d_in[3];
    const float* b_qkv  = (const float*)d_in[4];
    const float* w_proj = (const float*)d_in[5];
    const float* b_proj = (const float*)d_in[6];
    float* out = (float*)d_out;

    float *xnT, *hT;
    __half *qh, *ql, *kh, *kl, *vh, *vl;
    cudaGetSymbolAddress((void**)&xnT, g_xnT);
    cudaGetSymbolAddress((void**)&hT,  g_hT);
    cudaGetSymbolAddress((void**)&qh,  g_qh);
    cudaGetSymbolAddress((void**)&ql,  g_ql);
    cudaGetSymbolAddress((void**)&kh,  g_kh);
    cudaGetSymbolAddress((void**)&kl,  g_kl);
    cudaGetSymbolAddress((void**)&vh,  g_vh);
    cudaGetSymbolAddress((void**)&vl,  g_vl);

    // GEMM smem: half tiles 64K + 2 fp32 stages (2*(128+128)*272 = 139264) + slack
    const int SM_GEMM = 65536 + 2 * (128 * 272 + 128 * 272) + 1024;   // 205824
    const int SM_ATTN = 16384 + 2 * 32768 + 1024;                     // 82944 -> 2 CTAs/SM
    cudaFuncSetAttribute(mma_gemm<128,128,0>, cudaFuncAttributeMaxDynamicSharedMemorySize, SM_GEMM);
    cudaFuncSetAttribute(mma_gemm<128,128,3>, cudaFuncAttributeMaxDynamicSharedMemorySize, SM_GEMM);
    cudaFuncSetAttribute(attn_kernel,         cudaFuncAttributeMaxDynamicSharedMemorySize, SM_ATTN);

    // 1) GroupNorm + transpose
    gn_stats_kernel<<<Bn * NG, 256>>>(x);
    gn_apply_T_kernel<<<dim3(32, 16, 8), dim3(32, 8)>>>(x, gamma, beta);

    // 2) QKV GEMM -> pre-split fp16 hi/lo q/k/v
    mma_gemm<128,128,0><<<dim3(8, 12, 8), 256, SM_GEMM>>>(
        w_qkv, 512, 0, xnT, 512, 524288, 512, b_qkv, nullptr,
        nullptr, qh, ql, kh, kl, vh, vl);

    // 3) fused flash attention (128 thr, 2 CTAs/SM) -> hT (b, t, c)
    attn_kernel<<<dim3(16, 64), 128, SM_ATTN>>>(qh, ql, kh, kl, vh, vl, hT);

    // 4) proj GEMM + bias + residual -> out
    mma_gemm<128,128,3><<<dim3(8, 4, 8), 256, SM_GEMM>>>(
        w_proj, 512, 0, hT, 512, 524288, 512, b_proj, x,
        out, nullptr, nullptr, nullptr, nullptr, nullptr, nullptr);
}

// round 15
// speedup vs baseline: 1.1923x; 1.1923x over previous
#include <cuda_runtime.h>
#include <cuda_bf16.h>
#include <cuda_fp16.h>
#include <cstdint>

#define Bn 8
#define Cn 512
#define Sn 1024
#define NH 8
#define NG 32
#define EPSV 1e-5f

// ---------------------------------------------------------------------------
// Static device scratch (allocation-free rule)
// ---------------------------------------------------------------------------
__device__ float  g_xnT[(long)Bn * Sn * Cn];            // (b, s, c) fp32
__device__ __half g_qh[(long)Bn * NH * Sn * 64];        // (bh, t, d) hi
__device__ __half g_ql[(long)Bn * NH * Sn * 64];        // lo
__device__ __half g_kh[(long)Bn * NH * Sn * 64];        // (bh, s, d)
__device__ __half g_kl[(long)Bn * NH * Sn * 64];
__device__ __half g_vh[(long)Bn * NH * 64 * Sn];        // (bh, d, s)
__device__ __half g_vl[(long)Bn * NH * 64 * Sn];
__device__ float  g_hT[(long)Bn * Sn * Cn];             // (b, t, c) fp32
__device__ float  g_mean[Bn * NG];
__device__ float  g_rstd[Bn * NG];

// ---------------------------------------------------------------------------
// PTX helpers (base ISA only)
// ---------------------------------------------------------------------------
__device__ __forceinline__ uint32_t smem_u32(const void* p) {
    uint32_t a;
    asm("{ .reg .u64 t; cvta.to.shared.u64 t, %1; cvt.u32.u64 %0, t; }" : "=r"(a) : "l"(p));
    return a;
}
__device__ __forceinline__ void ldsm4(uint32_t* r, uint32_t addr) {
    asm volatile("ldmatrix.sync.aligned.m8n8.x4.shared.b16 {%0,%1,%2,%3}, [%4];"
        : "=r"(r[0]), "=r"(r[1]), "=r"(r[2]), "=r"(r[3]) : "r"(addr));
}
__device__ __forceinline__ void mma16816(float* c, const uint32_t* a, const uint32_t* b) {
    asm volatile("mma.sync.aligned.m16n8k16.row.col.f32.f16.f16.f32 "
        "{%0,%1,%2,%3}, {%4,%5,%6,%7}, {%8,%9}, {%0,%1,%2,%3};"
        : "+f"(c[0]), "+f"(c[1]), "+f"(c[2]), "+f"(c[3])
        : "r"(a[0]), "r"(a[1]), "r"(a[2]), "r"(a[3]), "r"(b[0]), "r"(b[1]));
}
__device__ __forceinline__ uint32_t packh2(float a, float b) {
    __half2 t = __floats2half2_rn(a, b);
    return *reinterpret_cast<uint32_t*>(&t);
}
#define SWZ(o)    ((o) ^ (((o) >> 3) & 0x70))
#define CP16(d, s)   asm volatile("cp.async.cg.shared.global [%0], [%1], 16;" :: "r"(d), "l"(s) : "memory")
#define CP_COMMIT()  asm volatile("cp.async.commit_group;" ::: "memory")
#define CP_WAIT0()   asm volatile("cp.async.wait_group 0;" ::: "memory")
#define CP_WAIT1()   asm volatile("cp.async.wait_group 1;" ::: "memory")

__device__ __forceinline__ void split_h(float v, __half& h, __half& l) {
    h = __float2half_rn(v);
    l = __float2half_rn(v - __half2float(h));
}

// ---------------------------------------------------------------------------
// Tile loader (fp32 -> fp16 hi/lo, SW128 rows of 64 halfs), THREADS threads
// ---------------------------------------------------------------------------
template<int ROWS, int THREADS>
__device__ __forceinline__ void load_tile(char* hiT, char* loT,
        const float* __restrict__ src, long ld, int r0, int k0, int tid) {
    #pragma unroll
    for (int it = 0; it < ROWS * 16 / THREADS; it++) {
        int idx = it * THREADS + tid;
        int row = idx >> 4;
        int k4  = (idx & 15) << 2;
        float4 v = *(const float4*)(src + (long)(r0 + row) * ld + k0 + k4);
        __half2 h0 = __floats2half2_rn(v.x, v.y);
        __half2 h1 = __floats2half2_rn(v.z, v.w);
        float2 f0 = __half22float2(h0), f1 = __half22float2(h1);
        uint2 hi = make_uint2(*reinterpret_cast<uint32_t*>(&h0),
                              *reinterpret_cast<uint32_t*>(&h1));
        uint2 lo = make_uint2(packh2(v.x - f0.x, v.y - f0.y),
                              packh2(v.z - f1.x, v.w - f1.y));
        uint32_t sw = SWZ((uint32_t)row * 128u + (uint32_t)k4 * 2u);
        *reinterpret_cast<uint2*>(hiT + sw) = hi;
        *reinterpret_cast<uint2*>(loT + sw) = lo;
    }
}

// ---------------------------------------------------------------------------
// HMMA GEMM (fp16x3):  D[m,n] = sum_k A[m,k]*B[n,k], both K-major fp32.
// 128 threads, BM=128, BN=64, 2x2 warp grid (warp tile 64x32), 3 CTAs/SM.
// MODE 0: QKV -> scatter into half hi/lo q/k/v tensors (+bias), z=b
// MODE 3: proj (+bias +residual) -> out fp32, z=b
// ---------------------------------------------------------------------------
template<int MODE>
__global__ __launch_bounds__(128, 3)
void mma_gemm(const float* __restrict__ A, long ldA, long Az,
              const float* __restrict__ Bp, long ldB, long Bz,
              int K, const float* __restrict__ bias, const float* __restrict__ resid,
              float* __restrict__ OutF,
              __half* __restrict__ H0, __half* __restrict__ H1,
              __half* __restrict__ H2, __half* __restrict__ H3,
              __half* __restrict__ H4, __half* __restrict__ H5)
{
    constexpr int BM = 128, BN = 64;
    extern __shared__ char smraw[];
    uint32_t sb = smem_u32(smraw);
    uint32_t aB = (sb + 1023u) & ~1023u;
    char* base = smraw + (aB - sb);
    char* aHi = base;
    char* aLo = base + BM * 128;
    char* bHi = base + 2 * BM * 128;
    char* bLo = bHi + BN * 128;
    uint32_t aHiU = aB, aLoU = aB + BM * 128;
    uint32_t bHiU = aB + 2 * BM * 128, bLoU = bHiU + BN * 128;
    float* stage = (float*)base;

    int tid = threadIdx.x, wid = tid >> 5, lane = tid & 31;
    int wm = wid >> 1, wn = wid & 1;          // 2x2 warp grid
    int m0 = blockIdx.y * BM, n0 = blockIdx.x * BN, z = blockIdx.z;
    const float* Ab = A  + (long)z * Az;
    const float* Bb = Bp + (long)z * Bz;

    float acc[4][4][4];
    #pragma unroll
    for (int mi = 0; mi < 4; mi++)
        #pragma unroll
        for (int ni = 0; ni < 4; ni++)
            #pragma unroll
            for (int j = 0; j < 4; j++) acc[mi][ni][j] = 0.f;

    int nPass = K >> 6;
    for (int pass = 0; pass < nPass; ++pass) {
        int k0 = pass << 6;
        load_tile<BM, 128>(aHi, aLo, Ab, ldA, m0, k0, tid);
        load_tile<BN, 128>(bHi, bLo, Bb, ldB, n0, k0, tid);
        __syncthreads();

        #pragma unroll
        for (int kc = 0; kc < 4; kc++) {
            uint32_t ah[4][4], al[4][4], bhf[4][2], blf[4][2];
            #pragma unroll
            for (int mi = 0; mi < 4; mi++) {
                int row = wm * 64 + mi * 16 + (lane & 15);
                uint32_t sw = SWZ((uint32_t)row * 128u + kc * 32u + ((lane >> 4) << 4));
                ldsm4(ah[mi], aHiU + sw);
                ldsm4(al[mi], aLoU + sw);
            }
            #pragma unroll
            for (int g = 0; g < 2; g++) {
                int nr = wn * 32 + g * 16 + (lane & 7) + ((lane >> 4) & 1) * 8;
                uint32_t sw = SWZ((uint32_t)nr * 128u + kc * 32u + (((lane >> 3) & 1) << 4));
                uint32_t t4[4];
                ldsm4(t4, bHiU + sw);
                bhf[g*2][0] = t4[0]; bhf[g*2][1] = t4[1];
                bhf[g*2+1][0] = t4[2]; bhf[g*2+1][1] = t4[3];
                ldsm4(t4, bLoU + sw);
                blf[g*2][0] = t4[0]; blf[g*2][1] = t4[1];
                blf[g*2+1][0] = t4[2]; blf[g*2+1][1] = t4[3];
            }
            #pragma unroll
            for (int mi = 0; mi < 4; mi++)
                #pragma unroll
                for (int ni = 0; ni < 4; ni++) {
                    mma16816(acc[mi][ni], ah[mi], bhf[ni]);
                    mma16816(acc[mi][ni], al[mi], bhf[ni]);
                    mma16816(acc[mi][ni], ah[mi], blf[ni]);
                }
        }
        __syncthreads();
    }

    constexpr int SLD = BN + 2;
    #pragma unroll
    for (int mi = 0; mi < 4; mi++)
        #pragma unroll
        for (int ni = 0; ni < 4; ni++) {
            int r = wm * 64 + mi * 16 + (lane >> 2);
            int c = wn * 32 + ni * 8 + (lane & 3) * 2;
            *(float2*)&stage[r * SLD + c] = make_float2(acc[mi][ni][0], acc[mi][ni][1]);
            *(float2*)&stage[(r + 8) * SLD + c] = make_float2(acc[mi][ni][2], acc[mi][ni][3]);
        }
    __syncthreads();

    if (MODE == 0) {
        int three = m0 >> 9;
        int b = z;
        if (three < 2) {
            __half* dh = three ? H2 : H0;
            __half* dl = three ? H3 : H1;
            for (int cc = wid; cc < BN; cc += 4) {
                int t = n0 + cc;
                #pragma unroll
                for (int ii = 0; ii < BM / 32; ii++) {
                    int r = lane + 32 * ii;
                    int o = (m0 + r) & 511;
                    int h = o >> 6, d = o & 63;
                    float val = stage[r * SLD + cc] + bias[m0 + r];
                    __half hi, lo; split_h(val, hi, lo);
                    long idx = (((long)(b * 8 + h) << 10) + t) * 64 + d;
                    dh[idx] = hi; dl[idx] = lo;
                }
            }
        } else {
            for (int r = wid; r < BM; r += 4) {
                int o = (m0 + r) & 511;
                int h = o >> 6, d = o & 63;
                float bv = bias[m0 + r];
                long basei = ((long)(b * 8 + h) * 64 + d) * 1024 + n0;
                #pragma unroll
                for (int j = 0; j < BN / 32; j++) {
                    int c = lane + 32 * j;
                    float val = stage[r * SLD + c] + bv;
                    __half hi, lo; split_h(val, hi, lo);
                    H4[basei + c] = hi; H5[basei + c] = lo;
                }
            }
        }
    } else {
        for (int r = wid; r < BM; r += 4) {
            int o = m0 + r;
            float bv = bias[o];
            long basei = (long)z * 524288 + (long)o * 1024 + n0;
            #pragma unroll
            for (int j = 0; j < BN / 32; j++) {
                int c = lane + 32 * j;
                OutF[basei + c] = stage[r * SLD + c] + bv + resid[basei + c];
            }
        }
    }
}

// ---------------------------------------------------------------------------
// Fused flash attention: 128-thread CTAs (4 warps), 64 Q rows per CTA,
// SK=64 keys/stage, double-buffered, 2 CTAs/SM.
// SMEM: Q hi 0..8K, Q lo 8K..16K; stage s @16K + s*32K:
//       K hi +0, K lo +8K, V hi +16K, V lo +24K   (all 64x64 half tiles)
// ---------------------------------------------------------------------------
__global__ __launch_bounds__(128)
void attn_kernel(const __half* __restrict__ qh, const __half* __restrict__ ql,
                 const __half* __restrict__ kh, const __half* __restrict__ kl,
                 const __half* __restrict__ vh, const __half* __restrict__ vl,
                 float* __restrict__ hT)
{
    extern __shared__ char smraw[];
    uint32_t sb = smem_u32(smraw);
    uint32_t base = (sb + 1023u) & ~1023u;

    int tid = threadIdx.x, wid = tid >> 5, lane = tid & 31;
    int bh = blockIdx.y;
    int t0 = blockIdx.x * 64;
    int b = bh >> 3, h = bh & 7;

    // ---- prologue: Q hi/lo (64 rows) ----
    #pragma unroll
    for (int i = 0; i < 4; i++) {
        int id = tid + i * 128;
        int row = id >> 3, c = id & 7;
        uint32_t sw = SWZ((uint32_t)row * 128u + c * 16u);
        long off = ((long)bh * 1024 + t0 + row) * 64 + c * 8;
        CP16(base + sw,         qh + off);
        CP16(base + 8192u + sw, ql + off);
    }

    auto load_kv = [&](int it, int s) {
        uint32_t stg = base + 16384u + (uint32_t)s * 32768u;
        int s0 = it * 64;
        #pragma unroll
        for (int i = 0; i < 4; i++) {
            int id = tid + i * 128;
            int row = id >> 3, c = id & 7;
            uint32_t sw = SWZ((uint32_t)row * 128u + c * 16u);
            long koff = ((long)bh * 1024 + s0 + row) * 64 + c * 8;
            CP16(stg + sw,          kh + koff);
            CP16(stg + 8192u + sw,  kl + koff);
            long voff = ((long)bh * 64 + row) * 1024 + s0 + c * 8;
            CP16(stg + 16384u + sw, vh + voff);
            CP16(stg + 24576u + sw, vl + voff);
        }
        CP_COMMIT();
    };
    load_kv(0, 0);

    float m0v = -1e30f, m1v = -1e30f, l0 = 0.f, l1 = 0.f;
    float acc_o[8][4];
    #pragma unroll
    for (int ni = 0; ni < 8; ni++)
        #pragma unroll
        for (int j = 0; j < 4; j++) acc_o[ni][j] = 0.f;

    for (int it = 0; it < 16; it++) {
        if (it < 15) { load_kv(it + 1, (it + 1) & 1); CP_WAIT1(); }
        else CP_WAIT0();
        __syncthreads();
        uint32_t stg = base + 16384u + (uint32_t)(it & 1) * 32768u;

        // ---- S = Q K^T over 64 keys (fp16x3) ----
        float s_acc[8][4];
        #pragma unroll
        for (int ni = 0; ni < 8; ni++)
            #pragma unroll
            for (int j = 0; j < 4; j++) s_acc[ni][j] = 0.f;

        #pragma unroll
        for (int kc = 0; kc < 4; kc++) {
            uint32_t ah[4], al[4], th[4][4], tl[4][4];
            {
                int row = wid * 16 + (lane & 15);
                uint32_t sw = SWZ((uint32_t)row * 128u + kc * 32u + ((lane >> 4) << 4));
                ldsm4(ah, base + sw);
                ldsm4(al, base + 8192u + sw);
            }
            #pragma unroll
            for (int g = 0; g < 4; g++) {
                int nr = g * 16 + (lane & 7) + ((lane >> 4) & 1) * 8;
                uint32_t sw = SWZ((uint32_t)nr * 128u + kc * 32u + (((lane >> 3) & 1) << 4));
                ldsm4(th[g], stg + sw);
                ldsm4(tl[g], stg + 8192u + sw);
            }
            #pragma unroll
            for (int g = 0; g < 4; g++) {
                mma16816(s_acc[2*g],   ah, th[g]);
                mma16816(s_acc[2*g+1], ah, th[g] + 2);
            }
            #pragma unroll
            for (int g = 0; g < 4; g++) {
                mma16816(s_acc[2*g],   al, th[g]);
                mma16816(s_acc[2*g+1], al, th[g] + 2);
            }
            #pragma unroll
            for (int g = 0; g < 4; g++) {
                mma16816(s_acc[2*g],   ah, tl[g]);
                mma16816(s_acc[2*g+1], ah, tl[g] + 2);
            }
        }

        // ---- online softmax ----
        float mx0 = -1e30f, mx1 = -1e30f;
        #pragma unroll
        for (int ni = 0; ni < 8; ni++) {
            s_acc[ni][0] *= 0.125f; s_acc[ni][1] *= 0.125f;
            s_acc[ni][2] *= 0.125f; s_acc[ni][3] *= 0.125f;
            mx0 = fmaxf(mx0, fmaxf(s_acc[ni][0], s_acc[ni][1]));
            mx1 = fmaxf(mx1, fmaxf(s_acc[ni][2], s_acc[ni][3]));
        }
        mx0 = fmaxf(mx0, __shfl_xor_sync(0xffffffffu, mx0, 1));
        mx0 = fmaxf(mx0, __shfl_xor_sync(0xffffffffu, mx0, 2));
        mx1 = fmaxf(mx1, __shfl_xor_sync(0xffffffffu, mx1, 1));
        mx1 = fmaxf(mx1, __shfl_xor_sync(0xffffffffu, mx1, 2));
        float mn0 = fmaxf(m0v, mx0), mn1 = fmaxf(m1v, mx1);
        float cr0 = __expf(m0v - mn0), cr1 = __expf(m1v - mn1);
        m0v = mn0; m1v = mn1;
        float sm0 = 0.f, sm1 = 0.f;
        #pragma unroll
        for (int ni = 0; ni < 8; ni++) {
            s_acc[ni][0] = __expf(s_acc[ni][0] - m0v);
            s_acc[ni][1] = __expf(s_acc[ni][1] - m0v);
            s_acc[ni][2] = __expf(s_acc[ni][2] - m1v);
            s_acc[ni][3] = __expf(s_acc[ni][3] - m1v);
            sm0 += s_acc[ni][0] + s_acc[ni][1];
            sm1 += s_acc[ni][2] + s_acc[ni][3];
        }
        sm0 += __shfl_xor_sync(0xffffffffu, sm0, 1);
        sm0 += __shfl_xor_sync(0xffffffffu, sm0, 2);
        sm1 += __shfl_xor_sync(0xffffffffu, sm1, 1);
        sm1 += __shfl_xor_sync(0xffffffffu, sm1, 2);
        l0 = l0 * cr0 + sm0;
        l1 = l1 * cr1 + sm1;
        #pragma unroll
        for (int ni = 0; ni < 8; ni++) {
            acc_o[ni][0] *= cr0; acc_o[ni][1] *= cr0;
            acc_o[ni][2] *= cr1; acc_o[ni][3] *= cr1;
        }

        // ---- O += P V (fp16x3) ----
        #pragma unroll
        for (int kp = 0; kp < 4; kp++) {
            uint32_t paf[4], plf[4];
            #pragma unroll
            for (int q2 = 0; q2 < 2; q2++) {
                int ni = 2 * kp + q2;
                __half2 hA = __floats2half2_rn(s_acc[ni][0], s_acc[ni][1]);
                __half2 hB = __floats2half2_rn(s_acc[ni][2], s_acc[ni][3]);
                float2 fA = __half22float2(hA), fB = __half22float2(hB);
                paf[2*q2]   = *reinterpret_cast<uint32_t*>(&hA);
                paf[2*q2+1] = *reinterpret_cast<uint32_t*>(&hB);
                plf[2*q2]   = packh2(s_acc[ni][0] - fA.x, s_acc[ni][1] - fA.y);
                plf[2*q2+1] = packh2(s_acc[ni][2] - fB.x, s_acc[ni][3] - fB.y);
            }
            uint32_t tv[4][4], tw[4][4];
            #pragma unroll
            for (int g2 = 0; g2 < 4; g2++) {
                int nr = g2 * 16 + (lane & 7) + ((lane >> 4) & 1) * 8;
                uint32_t sw = SWZ((uint32_t)nr * 128u + kp * 32u + (((lane >> 3) & 1) << 4));
                ldsm4(tv[g2], stg + 16384u + sw);
                ldsm4(tw[g2], stg + 24576u + sw);
            }
            #pragma unroll
            for (int g2 = 0; g2 < 4; g2++) {
                mma16816(acc_o[2*g2],   paf, tv[g2]);
                mma16816(acc_o[2*g2+1], paf, tv[g2] + 2);
            }
            #pragma unroll
            for (int g2 = 0; g2 < 4; g2++) {
                mma16816(acc_o[2*g2],   plf, tv[g2]);
                mma16816(acc_o[2*g2+1], plf, tv[g2] + 2);
            }
            #pragma unroll
            for (int g2 = 0; g2 < 4; g2++) {
                mma16816(acc_o[2*g2],   paf, tw[g2]);
                mma16816(acc_o[2*g2+1], paf, tw[g2] + 2);
            }
        }
        __syncthreads();
    }

    // ---- epilogue: hT[b, t, h*64+d] = O / l ----
    float inv0 = 1.f / l0, inv1 = 1.f / l1;
    int tr = t0 + wid * 16 + (lane >> 2);
    #pragma unroll
    for (int ni = 0; ni < 8; ni++) {
        int d0 = ni * 8 + (lane & 3) * 2;
        *(float2*)&hT[((long)b * 1024 + tr) * 512 + h * 64 + d0] =
            make_float2(acc_o[ni][0] * inv0, acc_o[ni][1] * inv0);
        *(float2*)&hT[((long)b * 1024 + tr + 8) * 512 + h * 64 + d0] =
            make_float2(acc_o[ni][2] * inv1, acc_o[ni][3] * inv1);
    }
}

// ---------------------------------------------------------------------------
// Reductions, GroupNorm
// ---------------------------------------------------------------------------
__device__ __forceinline__ float warp_sum(float v) {
    #pragma unroll
    for (int o = 16; o; o >>= 1) v += __shfl_xor_sync(0xffffffffu, v, o);
    return v;
}
__device__ __forceinline__ float block_sum(float v, float* sh) {
    int lane = threadIdx.x & 31, w = threadIdx.x >> 5, nw = blockDim.x >> 5;
    v = warp_sum(v);
    if (lane == 0) sh[w] = v;
    __syncthreads();
    if (w == 0) {
        float r = (lane < nw) ? sh[lane] : 0.f;
        r = warp_sum(r);
        if (lane == 0) sh[0] = r;
    }
    __syncthreads();
    float r = sh[0];
    __syncthreads();
    return r;
}

__global__ void gn_stats_kernel(const float* __restrict__ x) {
    __shared__ float sh[32];
    int bg = blockIdx.x;
    const float4* p = (const float4*)(x + (long)bg * 16384);
    float s = 0.f, s2 = 0.f;
    for (int i = threadIdx.x; i < 4096; i += blockDim.x) {
        float4 v = p[i];
        s  += v.x + v.y + v.z + v.w;
        s2 += v.x*v.x + v.y*v.y + v.z*v.z + v.w*v.w;
    }
    s  = block_sum(s,  sh);
    s2 = block_sum(s2, sh);
    if (threadIdx.x == 0) {
        float mu  = s * (1.f / 16384.f);
        float var = s2 * (1.f / 16384.f) - mu * mu;
        g_mean[bg] = mu;
        g_rstd[bg] = rsqrtf(var + EPSV);
    }
}

__global__ void gn_apply_T_kernel(const float* __restrict__ x,
                                  const float* __restrict__ gamma,
                                  const float* __restrict__ beta) {
    __shared__ float t[32][33];
    int b = blockIdx.z, c0 = blockIdx.y * 32, s0 = blockIdx.x * 32;
    for (int i = threadIdx.y; i < 32; i += 8) {
        int c = c0 + i;
        int bg = b * 32 + (c >> 4);
        float a = g_rstd[bg] * gamma[c];
        float bb = beta[c] - g_mean[bg] * a;
        t[i][threadIdx.x] = x[((long)b * 512 + c) * 1024 + s0 + threadIdx.x] * a + bb;
    }
    __syncthreads();
    for (int i = threadIdx.y; i < 32; i += 8)
        g_xnT[((long)b * 1024 + s0 + i) * 512 + c0 + threadIdx.x] = t[threadIdx.x][i];
}

// ---------------------------------------------------------------------------
// Launch
// ---------------------------------------------------------------------------
extern "C" void kernel_launch(void* const* d_in, const int* in_sizes, int n_in,
                              void* d_out, int out_size) {
    const float* x      = (const float*)d_in[0];
    const float* gamma  = (const float*)d_in[1];
    const float* beta   = (const float*)d_in[2];
    const float* w_qkv  = (const float*)d_in[3];
    const float* b_qkv  = (const float*)d_in[4];
    const float* w_proj = (const float*)d_in[5];
    const float* b_proj = (const float*)d_in[6];
    float* out = (float*)d_out;

    float *xnT, *hT;
    __half *qh, *ql, *kh, *kl, *vh, *vl;
    cudaGetSymbolAddress((void**)&xnT, g_xnT);
    cudaGetSymbolAddress((void**)&hT,  g_hT);
    cudaGetSymbolAddress((void**)&qh,  g_qh);
    cudaGetSymbolAddress((void**)&ql,  g_ql);
    cudaGetSymbolAddress((void**)&kh,  g_kh);
    cudaGetSymbolAddress((void**)&kl,  g_kl);
    cudaGetSymbolAddress((void**)&vh,  g_vh);
    cudaGetSymbolAddress((void**)&vl,  g_vl);

    // GEMM smem: (128+64) rows x 128B x 2 (hi/lo) = 49152; stage 128*66*4 = 33792 fits
    const int SM_GEMM = 49152 + 1024;
    const int SM_ATTN = 16384 + 2 * 32768 + 1024;   // 82944 -> 2 CTAs/SM
    cudaFuncSetAttribute(mma_gemm<0>, cudaFuncAttributeMaxDynamicSharedMemorySize, SM_GEMM);
    cudaFuncSetAttribute(mma_gemm<3>, cudaFuncAttributeMaxDynamicSharedMemorySize, SM_GEMM);
    cudaFuncSetAttribute(attn_kernel, cudaFuncAttributeMaxDynamicSharedMemorySize, SM_ATTN);

    // 1) GroupNorm + transpose
    gn_stats_kernel<<<Bn * NG, 256>>>(x);
    gn_apply_T_kernel<<<dim3(32, 16, 8), dim3(32, 8)>>>(x, gamma, beta);

    // 2) QKV GEMM -> pre-split fp16 hi/lo q/k/v  (1536 CTAs of 128 thr, 3/SM)
    mma_gemm<0><<<dim3(16, 12, 8), 128, SM_GEMM>>>(
        w_qkv, 512, 0, xnT, 512, 524288, 512, b_qkv, nullptr,
        nullptr, qh, ql, kh, kl, vh, vl);

    // 3) fused flash attention (128 thr, 2 CTAs/SM) -> hT (b, t, c)
    attn_kernel<<<dim3(16, 64), 128, SM_ATTN>>>(qh, ql, kh, kl, vh, vl, hT);

    // 4) proj GEMM + bias + residual -> out  (512 CTAs of 128 thr, 3/SM)
    mma_gemm<3><<<dim3(16, 4, 8), 128, SM_GEMM>>>(
        w_proj, 512, 0, hT, 512, 524288, 512, b_proj, x,
        out, nullptr, nullptr, nullptr, nullptr, nullptr, nullptr);
}

// round 16
// speedup vs baseline: 1.3349x; 1.1196x over previous
#include <cuda_runtime.h>
#include <cuda_bf16.h>
#include <cuda_fp16.h>
#include <cstdint>

#define Bn 8
#define Cn 512
#define Sn 1024
#define NH 8
#define NG 32
#define EPSV 1e-5f

// ---------------------------------------------------------------------------
// Static device scratch (allocation-free rule)
// ---------------------------------------------------------------------------
__device__ __half g_xnTh[(long)Bn * Sn * Cn];   // (b, s, c) hi
__device__ __half g_xnTl[(long)Bn * Sn * Cn];   // lo
__device__ __half g_wqh[1536 * 512];
__device__ __half g_wql[1536 * 512];
__device__ __half g_wph[512 * 512];
__device__ __half g_wpl[512 * 512];
__device__ __half g_qh[(long)Bn * NH * Sn * 64];  // (bh, t, d)
__device__ __half g_ql[(long)Bn * NH * Sn * 64];
__device__ __half g_kh[(long)Bn * NH * Sn * 64];  // (bh, s, d)
__device__ __half g_kl[(long)Bn * NH * Sn * 64];
__device__ __half g_vh[(long)Bn * NH * 64 * Sn];  // (bh, d, s)
__device__ __half g_vl[(long)Bn * NH * 64 * Sn];
__device__ __half g_hTh[(long)Bn * Sn * Cn];      // (b, t, c)
__device__ __half g_hTl[(long)Bn * Sn * Cn];
__device__ float  g_mean[Bn * NG];
__device__ float  g_rstd[Bn * NG];

// ---------------------------------------------------------------------------
// PTX helpers (base ISA only)
// ---------------------------------------------------------------------------
__device__ __forceinline__ uint32_t smem_u32(const void* p) {
    uint32_t a;
    asm("{ .reg .u64 t; cvta.to.shared.u64 t, %1; cvt.u32.u64 %0, t; }" : "=r"(a) : "l"(p));
    return a;
}
__device__ __forceinline__ void ldsm4(uint32_t* r, uint32_t addr) {
    asm volatile("ldmatrix.sync.aligned.m8n8.x4.shared.b16 {%0,%1,%2,%3}, [%4];"
        : "=r"(r[0]), "=r"(r[1]), "=r"(r[2]), "=r"(r[3]) : "r"(addr));
}
__device__ __forceinline__ void mma16816(float* c, const uint32_t* a, const uint32_t* b) {
    asm volatile("mma.sync.aligned.m16n8k16.row.col.f32.f16.f16.f32 "
        "{%0,%1,%2,%3}, {%4,%5,%6,%7}, {%8,%9}, {%0,%1,%2,%3};"
        : "+f"(c[0]), "+f"(c[1]), "+f"(c[2]), "+f"(c[3])
        : "r"(a[0]), "r"(a[1]), "r"(a[2]), "r"(a[3]), "r"(b[0]), "r"(b[1]));
}
__device__ __forceinline__ uint32_t packh2(float a, float b) {
    __half2 t = __floats2half2_rn(a, b);
    return *reinterpret_cast<uint32_t*>(&t);
}
#define SWZ(o)    ((o) ^ (((o) >> 3) & 0x70))
#define CP16(d, s)   asm volatile("cp.async.cg.shared.global [%0], [%1], 16;" :: "r"(d), "l"(s) : "memory")
#define CP_COMMIT()  asm volatile("cp.async.commit_group;" ::: "memory")
#define CP_WAIT0()   asm volatile("cp.async.wait_group 0;" ::: "memory")
#define CP_WAIT1()   asm volatile("cp.async.wait_group 1;" ::: "memory")

__device__ __forceinline__ void split_h(float v, __half& h, __half& l) {
    h = __float2half_rn(v);
    l = __float2half_rn(v - __half2float(h));
}

// ---------------------------------------------------------------------------
// Weight pre-split: fp32 -> fp16 hi/lo (w_qkv then w_proj)
// ---------------------------------------------------------------------------
__global__ void wsplit_kernel(const float* __restrict__ wq, const float* __restrict__ wp) {
    long i4 = ((long)blockIdx.x * blockDim.x + threadIdx.x) * 4;
    const float* src; __half *dh, *dl;
    if (i4 < 786432) { src = wq + i4; dh = g_wqh + i4; dl = g_wql + i4; }
    else { long j = i4 - 786432; src = wp + j; dh = g_wph + j; dl = g_wpl + j; }
    float4 v = *(const float4*)src;
    __half2 h0 = __floats2half2_rn(v.x, v.y), h1 = __floats2half2_rn(v.z, v.w);
    float2 f0 = __half22float2(h0), f1 = __half22float2(h1);
    __half2 l0 = __floats2half2_rn(v.x - f0.x, v.y - f0.y);
    __half2 l1 = __floats2half2_rn(v.z - f1.x, v.w - f1.y);
    *(__half2*)(dh)     = h0; *(__half2*)(dh + 2) = h1;
    *(__half2*)(dl)     = l0; *(__half2*)(dl + 2) = l1;
}

// ---------------------------------------------------------------------------
// HMMA GEMM (fp16x3): D[m,n] = sum_k A[m,k]*B[n,k], pre-split half hi/lo inputs.
// 128 threads, BM=128, BN=64, 2x2 warp grid (warp tile 64x32), 3 CTAs/SM.
// Pure cp.async loader (no convert in hot loop), single-buffered.
// MODE 0: QKV -> scatter into half hi/lo q/k/v tensors (+bias), z=b
// MODE 3: proj (+bias +residual) -> out fp32, z=b
// ---------------------------------------------------------------------------
template<int MODE>
__global__ __launch_bounds__(128, 3)
void mma_gemm(const __half* __restrict__ Ahp, const __half* __restrict__ Alp, long ldA,
              const __half* __restrict__ Bhp, const __half* __restrict__ Blp,
              long ldB, long Bz, int K,
              const float* __restrict__ bias, const float* __restrict__ resid,
              float* __restrict__ OutF,
              __half* __restrict__ H0, __half* __restrict__ H1,
              __half* __restrict__ H2, __half* __restrict__ H3,
              __half* __restrict__ H4, __half* __restrict__ H5)
{
    constexpr int BM = 128, BN = 64;
    extern __shared__ char smraw[];
    uint32_t sb = smem_u32(smraw);
    uint32_t aB = (sb + 1023u) & ~1023u;
    char* base = smraw + (aB - sb);
    uint32_t aHiU = aB, aLoU = aB + BM * 128;
    uint32_t bHiU = aB + 2 * BM * 128, bLoU = bHiU + BN * 128;
    float* stage = (float*)base;

    int tid = threadIdx.x, wid = tid >> 5, lane = tid & 31;
    int wm = wid >> 1, wn = wid & 1;          // 2x2 warp grid
    int m0 = blockIdx.y * BM, n0 = blockIdx.x * BN, z = blockIdx.z;
    const __half* Bh = Bhp + (long)z * Bz;
    const __half* Bl = Blp + (long)z * Bz;

    float acc[4][4][4];
    #pragma unroll
    for (int mi = 0; mi < 4; mi++)
        #pragma unroll
        for (int ni = 0; ni < 4; ni++)
            #pragma unroll
            for (int j = 0; j < 4; j++) acc[mi][ni][j] = 0.f;

    int nPass = K >> 6;
    for (int pass = 0; pass < nPass; ++pass) {
        int k0 = pass << 6;
        // A tiles: 128 rows x 8 chunks (hi, lo)
        #pragma unroll
        for (int i = 0; i < 8; i++) {
            int id = tid + i * 128;
            int row = id >> 3, c = id & 7;
            uint32_t sw = SWZ((uint32_t)row * 128u + c * 16u);
            long off = (long)(m0 + row) * ldA + k0 + c * 8;
            CP16(aHiU + sw, Ahp + off);
            CP16(aLoU + sw, Alp + off);
        }
        // B tiles: 64 rows x 8 chunks (hi, lo)
        #pragma unroll
        for (int i = 0; i < 4; i++) {
            int id = tid + i * 128;
            int row = id >> 3, c = id & 7;
            uint32_t sw = SWZ((uint32_t)row * 128u + c * 16u);
            long off = (long)(n0 + row) * ldB + k0 + c * 8;
            CP16(bHiU + sw, Bh + off);
            CP16(bLoU + sw, Bl + off);
        }
        CP_COMMIT();
        CP_WAIT0();
        __syncthreads();

        #pragma unroll
        for (int kc = 0; kc < 4; kc++) {
            uint32_t ah[4][4], al[4][4], bhf[4][2], blf[4][2];
            #pragma unroll
            for (int mi = 0; mi < 4; mi++) {
                int row = wm * 64 + mi * 16 + (lane & 15);
                uint32_t sw = SWZ((uint32_t)row * 128u + kc * 32u + ((lane >> 4) << 4));
                ldsm4(ah[mi], aHiU + sw);
                ldsm4(al[mi], aLoU + sw);
            }
            #pragma unroll
            for (int g = 0; g < 2; g++) {
                int nr = wn * 32 + g * 16 + (lane & 7) + ((lane >> 4) & 1) * 8;
                uint32_t sw = SWZ((uint32_t)nr * 128u + kc * 32u + (((lane >> 3) & 1) << 4));
                uint32_t t4[4];
                ldsm4(t4, bHiU + sw);
                bhf[g*2][0] = t4[0]; bhf[g*2][1] = t4[1];
                bhf[g*2+1][0] = t4[2]; bhf[g*2+1][1] = t4[3];
                ldsm4(t4, bLoU + sw);
                blf[g*2][0] = t4[0]; blf[g*2][1] = t4[1];
                blf[g*2+1][0] = t4[2]; blf[g*2+1][1] = t4[3];
            }
            #pragma unroll
            for (int mi = 0; mi < 4; mi++)
                #pragma unroll
                for (int ni = 0; ni < 4; ni++) {
                    mma16816(acc[mi][ni], ah[mi], bhf[ni]);
                    mma16816(acc[mi][ni], al[mi], bhf[ni]);
                    mma16816(acc[mi][ni], ah[mi], blf[ni]);
                }
        }
        __syncthreads();
    }

    constexpr int SLD = BN + 2;
    #pragma unroll
    for (int mi = 0; mi < 4; mi++)
        #pragma unroll
        for (int ni = 0; ni < 4; ni++) {
            int r = wm * 64 + mi * 16 + (lane >> 2);
            int c = wn * 32 + ni * 8 + (lane & 3) * 2;
            *(float2*)&stage[r * SLD + c] = make_float2(acc[mi][ni][0], acc[mi][ni][1]);
            *(float2*)&stage[(r + 8) * SLD + c] = make_float2(acc[mi][ni][2], acc[mi][ni][3]);
        }
    __syncthreads();

    if (MODE == 0) {
        int three = m0 >> 9;
        int b = z;
        if (three < 2) {
            __half* dh = three ? H2 : H0;
            __half* dl = three ? H3 : H1;
            for (int cc = wid; cc < BN; cc += 4) {
                int t = n0 + cc;
                #pragma unroll
                for (int ii = 0; ii < BM / 32; ii++) {
                    int r = lane + 32 * ii;
                    int o = (m0 + r) & 511;
                    int h = o >> 6, d = o & 63;
                    float val = stage[r * SLD + cc] + bias[m0 + r];
                    __half hi, lo; split_h(val, hi, lo);
                    long idx = (((long)(b * 8 + h) << 10) + t) * 64 + d;
                    dh[idx] = hi; dl[idx] = lo;
                }
            }
        } else {
            for (int r = wid; r < BM; r += 4) {
                int o = (m0 + r) & 511;
                int h = o >> 6, d = o & 63;
                float bv = bias[m0 + r];
                long basei = ((long)(b * 8 + h) * 64 + d) * 1024 + n0;
                #pragma unroll
                for (int j = 0; j < BN / 32; j++) {
                    int c = lane + 32 * j;
                    float val = stage[r * SLD + c] + bv;
                    __half hi, lo; split_h(val, hi, lo);
                    H4[basei + c] = hi; H5[basei + c] = lo;
                }
            }
        }
    } else {
        for (int r = wid; r < BM; r += 4) {
            int o = m0 + r;
            float bv = bias[o];
            long basei = (long)z * 524288 + (long)o * 1024 + n0;
            #pragma unroll
            for (int j = 0; j < BN / 32; j++) {
                int c = lane + 32 * j;
                OutF[basei + c] = stage[r * SLD + c] + bv + resid[basei + c];
            }
        }
    }
}

// ---------------------------------------------------------------------------
// Fused flash attention: 128-thread CTAs (4 warps), 64 Q rows per CTA,
// Q fragments held in REGISTERS; smem = 2 x 32KB KV stages -> 3 CTAs/SM.
// Stage s @base + s*32K: K hi +0, K lo +8K, V hi +16K, V lo +24K (64x64 tiles)
// ---------------------------------------------------------------------------
__global__ __launch_bounds__(128, 3)
void attn_kernel(const __half* __restrict__ qh, const __half* __restrict__ ql,
                 const __half* __restrict__ kh, const __half* __restrict__ kl,
                 const __half* __restrict__ vh, const __half* __restrict__ vl,
                 __half* __restrict__ hTh, __half* __restrict__ hTl)
{
    extern __shared__ char smraw[];
    uint32_t sb = smem_u32(smraw);
    uint32_t base = (sb + 1023u) & ~1023u;

    int tid = threadIdx.x, wid = tid >> 5, lane = tid & 31;
    int bh = blockIdx.y;
    int t0 = blockIdx.x * 64;
    int b = bh >> 3, h = bh & 7;

    // ---- prologue: Q hi/lo through stage0 region, extract frags to regs ----
    #pragma unroll
    for (int i = 0; i < 4; i++) {
        int id = tid + i * 128;
        int row = id >> 3, c = id & 7;
        uint32_t sw = SWZ((uint32_t)row * 128u + c * 16u);
        long off = ((long)bh * 1024 + t0 + row) * 64 + c * 8;
        CP16(base + sw,         qh + off);
        CP16(base + 8192u + sw, ql + off);
    }
    CP_COMMIT();
    CP_WAIT0();
    __syncthreads();

    uint32_t qfh[4][4], qfl[4][4];
    #pragma unroll
    for (int kc = 0; kc < 4; kc++) {
        int row = wid * 16 + (lane & 15);
        uint32_t sw = SWZ((uint32_t)row * 128u + kc * 32u + ((lane >> 4) << 4));
        ldsm4(qfh[kc], base + sw);
        ldsm4(qfl[kc], base + 8192u + sw);
    }
    __syncthreads();   // all warps done with Q smem before stage0 KV overwrites

    auto load_kv = [&](int it, int s) {
        uint32_t stg = base + (uint32_t)s * 32768u;
        int s0 = it * 64;
        #pragma unroll
        for (int i = 0; i < 4; i++) {
            int id = tid + i * 128;
            int row = id >> 3, c = id & 7;
            uint32_t sw = SWZ((uint32_t)row * 128u + c * 16u);
            long koff = ((long)bh * 1024 + s0 + row) * 64 + c * 8;
            CP16(stg + sw,          kh + koff);
            CP16(stg + 8192u + sw,  kl + koff);
            long voff = ((long)bh * 64 + row) * 1024 + s0 + c * 8;
            CP16(stg + 16384u + sw, vh + voff);
            CP16(stg + 24576u + sw, vl + voff);
        }
        CP_COMMIT();
    };
    load_kv(0, 0);

    float m0v = -1e30f, m1v = -1e30f, l0 = 0.f, l1 = 0.f;
    float acc_o[8][4];
    #pragma unroll
    for (int ni = 0; ni < 8; ni++)
        #pragma unroll
        for (int j = 0; j < 4; j++) acc_o[ni][j] = 0.f;

    for (int it = 0; it < 16; it++) {
        if (it < 15) { load_kv(it + 1, (it + 1) & 1); CP_WAIT1(); }
        else CP_WAIT0();
        __syncthreads();
        uint32_t stg = base + (uint32_t)(it & 1) * 32768u;

        // ---- S = Q K^T over 64 keys (fp16x3, Q frags in regs) ----
        float s_acc[8][4];
        #pragma unroll
        for (int ni = 0; ni < 8; ni++)
            #pragma unroll
            for (int j = 0; j < 4; j++) s_acc[ni][j] = 0.f;

        #pragma unroll
        for (int kc = 0; kc < 4; kc++) {
            uint32_t th[4][4], tl[4][4];
            #pragma unroll
            for (int g = 0; g < 4; g++) {
                int nr = g * 16 + (lane & 7) + ((lane >> 4) & 1) * 8;
                uint32_t sw = SWZ((uint32_t)nr * 128u + kc * 32u + (((lane >> 3) & 1) << 4));
                ldsm4(th[g], stg + sw);
                ldsm4(tl[g], stg + 8192u + sw);
            }
            #pragma unroll
            for (int g = 0; g < 4; g++) {
                mma16816(s_acc[2*g],   qfh[kc], th[g]);
                mma16816(s_acc[2*g+1], qfh[kc], th[g] + 2);
            }
            #pragma unroll
            for (int g = 0; g < 4; g++) {
                mma16816(s_acc[2*g],   qfl[kc], th[g]);
                mma16816(s_acc[2*g+1], qfl[kc], th[g] + 2);
            }
            #pragma unroll
            for (int g = 0; g < 4; g++) {
                mma16816(s_acc[2*g],   qfh[kc], tl[g]);
                mma16816(s_acc[2*g+1], qfh[kc], tl[g] + 2);
            }
        }

        // ---- online softmax ----
        float mx0 = -1e30f, mx1 = -1e30f;
        #pragma unroll
        for (int ni = 0; ni < 8; ni++) {
            s_acc[ni][0] *= 0.125f; s_acc[ni][1] *= 0.125f;
            s_acc[ni][2] *= 0.125f; s_acc[ni][3] *= 0.125f;
            mx0 = fmaxf(mx0, fmaxf(s_acc[ni][0], s_acc[ni][1]));
            mx1 = fmaxf(mx1, fmaxf(s_acc[ni][2], s_acc[ni][3]));
        }
        mx0 = fmaxf(mx0, __shfl_xor_sync(0xffffffffu, mx0, 1));
        mx0 = fmaxf(mx0, __shfl_xor_sync(0xffffffffu, mx0, 2));
        mx1 = fmaxf(mx1, __shfl_xor_sync(0xffffffffu, mx1, 1));
        mx1 = fmaxf(mx1, __shfl_xor_sync(0xffffffffu, mx1, 2));
        float mn0 = fmaxf(m0v, mx0), mn1 = fmaxf(m1v, mx1);
        float cr0 = __expf(m0v - mn0), cr1 = __expf(m1v - mn1);
        m0v = mn0; m1v = mn1;
        float sm0 = 0.f, sm1 = 0.f;
        #pragma unroll
        for (int ni = 0; ni < 8; ni++) {
            s_acc[ni][0] = __expf(s_acc[ni][0] - m0v);
            s_acc[ni][1] = __expf(s_acc[ni][1] - m0v);
            s_acc[ni][2] = __expf(s_acc[ni][2] - m1v);
            s_acc[ni][3] = __expf(s_acc[ni][3] - m1v);
            sm0 += s_acc[ni][0] + s_acc[ni][1];
            sm1 += s_acc[ni][2] + s_acc[ni][3];
        }
        sm0 += __shfl_xor_sync(0xffffffffu, sm0, 1);
        sm0 += __shfl_xor_sync(0xffffffffu, sm0, 2);
        sm1 += __shfl_xor_sync(0xffffffffu, sm1, 1);
        sm1 += __shfl_xor_sync(0xffffffffu, sm1, 2);
        l0 = l0 * cr0 + sm0;
        l1 = l1 * cr1 + sm1;
        #pragma unroll
        for (int ni = 0; ni < 8; ni++) {
            acc_o[ni][0] *= cr0; acc_o[ni][1] *= cr0;
            acc_o[ni][2] *= cr1; acc_o[ni][3] *= cr1;
        }

        // ---- O += P V (fp16x3) ----
        #pragma unroll
        for (int kp = 0; kp < 4; kp++) {
            uint32_t paf[4], plf[4];
            #pragma unroll
            for (int q2 = 0; q2 < 2; q2++) {
                int ni = 2 * kp + q2;
                __half2 hA = __floats2half2_rn(s_acc[ni][0], s_acc[ni][1]);
                __half2 hB = __floats2half2_rn(s_acc[ni][2], s_acc[ni][3]);
                float2 fA = __half22float2(hA), fB = __half22float2(hB);
                paf[2*q2]   = *reinterpret_cast<uint32_t*>(&hA);
                paf[2*q2+1] = *reinterpret_cast<uint32_t*>(&hB);
                plf[2*q2]   = packh2(s_acc[ni][0] - fA.x, s_acc[ni][1] - fA.y);
                plf[2*q2+1] = packh2(s_acc[ni][2] - fB.x, s_acc[ni][3] - fB.y);
            }
            uint32_t tv[4][4], tw[4][4];
            #pragma unroll
            for (int g2 = 0; g2 < 4; g2++) {
                int nr = g2 * 16 + (lane & 7) + ((lane >> 4) & 1) * 8;
                uint32_t sw = SWZ((uint32_t)nr * 128u + kp * 32u + (((lane >> 3) & 1) << 4));
                ldsm4(tv[g2], stg + 16384u + sw);
                ldsm4(tw[g2], stg + 24576u + sw);
            }
            #pragma unroll
            for (int g2 = 0; g2 < 4; g2++) {
                mma16816(acc_o[2*g2],   paf, tv[g2]);
                mma16816(acc_o[2*g2+1], paf, tv[g2] + 2);
            }
            #pragma unroll
            for (int g2 = 0; g2 < 4; g2++) {
                mma16816(acc_o[2*g2],   plf, tv[g2]);
                mma16816(acc_o[2*g2+1], plf, tv[g2] + 2);
            }
            #pragma unroll
            for (int g2 = 0; g2 < 4; g2++) {
                mma16816(acc_o[2*g2],   paf, tw[g2]);
                mma16816(acc_o[2*g2+1], paf, tw[g2] + 2);
            }
        }
        __syncthreads();
    }

    // ---- epilogue: hT hi/lo halves ----
    float inv0 = 1.f / l0, inv1 = 1.f / l1;
    int tr = t0 + wid * 16 + (lane >> 2);
    #pragma unroll
    for (int ni = 0; ni < 8; ni++) {
        int d0 = ni * 8 + (lane & 3) * 2;
        long i0 = ((long)b * 1024 + tr) * 512 + h * 64 + d0;
        long i1 = ((long)b * 1024 + tr + 8) * 512 + h * 64 + d0;
        float v0 = acc_o[ni][0] * inv0, v1 = acc_o[ni][1] * inv0;
        float v2 = acc_o[ni][2] * inv1, v3 = acc_o[ni][3] * inv1;
        __half2 h0 = __floats2half2_rn(v0, v1);
        __half2 h1 = __floats2half2_rn(v2, v3);
        float2 f0 = __half22float2(h0), f1 = __half22float2(h1);
        *(__half2*)&hTh[i0] = h0;
        *(__half2*)&hTl[i0] = __floats2half2_rn(v0 - f0.x, v1 - f0.y);
        *(__half2*)&hTh[i1] = h1;
        *(__half2*)&hTl[i1] = __floats2half2_rn(v2 - f1.x, v3 - f1.y);
    }
}

// ---------------------------------------------------------------------------
// Reductions, GroupNorm
// ---------------------------------------------------------------------------
__device__ __forceinline__ float warp_sum(float v) {
    #pragma unroll
    for (int o = 16; o; o >>= 1) v += __shfl_xor_sync(0xffffffffu, v, o);
    return v;
}
__device__ __forceinline__ float block_sum(float v, float* sh) {
    int lane = threadIdx.x & 31, w = threadIdx.x >> 5, nw = blockDim.x >> 5;
    v = warp_sum(v);
    if (lane == 0) sh[w] = v;
    __syncthreads();
    if (w == 0) {
        float r = (lane < nw) ? sh[lane] : 0.f;
        r = warp_sum(r);
        if (lane == 0) sh[0] = r;
    }
    __syncthreads();
    float r = sh[0];
    __syncthreads();
    return r;
}

__global__ void gn_stats_kernel(const float* __restrict__ x) {
    __shared__ float sh[32];
    int bg = blockIdx.x;
    const float4* p = (const float4*)(x + (long)bg * 16384);
    float s = 0.f, s2 = 0.f;
    for (int i = threadIdx.x; i < 4096; i += blockDim.x) {
        float4 v = p[i];
        s  += v.x + v.y + v.z + v.w;
        s2 += v.x*v.x + v.y*v.y + v.z*v.z + v.w*v.w;
    }
    s  = block_sum(s,  sh);
    s2 = block_sum(s2, sh);
    if (threadIdx.x == 0) {
        float mu  = s * (1.f / 16384.f);
        float var = s2 * (1.f / 16384.f) - mu * mu;
        g_mean[bg] = mu;
        g_rstd[bg] = rsqrtf(var + EPSV);
    }
}

__global__ void gn_apply_T_kernel(const float* __restrict__ x,
                                  const float* __restrict__ gamma,
                                  const float* __restrict__ beta) {
    __shared__ float t[32][33];
    int b = blockIdx.z, c0 = blockIdx.y * 32, s0 = blockIdx.x * 32;
    for (int i = threadIdx.y; i < 32; i += 8) {
        int c = c0 + i;
        int bg = b * 32 + (c >> 4);
        float a = g_rstd[bg] * gamma[c];
        float bb = beta[c] - g_mean[bg] * a;
        t[i][threadIdx.x] = x[((long)b * 512 + c) * 1024 + s0 + threadIdx.x] * a + bb;
    }
    __syncthreads();
    for (int i = threadIdx.y; i < 32; i += 8) {
        float v = t[threadIdx.x][i];
        __half hi, lo; split_h(v, hi, lo);
        long idx = ((long)b * 1024 + s0 + i) * 512 + c0 + threadIdx.x;
        g_xnTh[idx] = hi; g_xnTl[idx] = lo;
    }
}

// ---------------------------------------------------------------------------
// Launch
// ---------------------------------------------------------------------------
extern "C" void kernel_launch(void* const* d_in, const int* in_sizes, int n_in,
                              void* d_out, int out_size) {
    const float* x      = (const float*)d_in[0];
    const float* gamma  = (const float*)d_in[1];
    const float* beta   = (const float*)d_in[2];
    const float* w_qkv  = (const float*)d_in[3];
    const float* b_qkv  = (const float*)d_in[4];
    const float* w_proj = (const float*)d_in[5];
    const float* b_proj = (const float*)d_in[6];
    float* out = (float*)d_out;

    __half *xnTh, *xnTl, *wqh, *wql, *wph, *wpl;
    __half *qh, *ql, *kh, *kl, *vh, *vl, *hTh, *hTl;
    cudaGetSymbolAddress((void**)&xnTh, g_xnTh);
    cudaGetSymbolAddress((void**)&xnTl, g_xnTl);
    cudaGetSymbolAddress((void**)&wqh,  g_wqh);
    cudaGetSymbolAddress((void**)&wql,  g_wql);
    cudaGetSymbolAddress((void**)&wph,  g_wph);
    cudaGetSymbolAddress((void**)&wpl,  g_wpl);
    cudaGetSymbolAddress((void**)&qh,   g_qh);
    cudaGetSymbolAddress((void**)&ql,   g_ql);
    cudaGetSymbolAddress((void**)&kh,   g_kh);
    cudaGetSymbolAddress((void**)&kl,   g_kl);
    cudaGetSymbolAddress((void**)&vh,   g_vh);
    cudaGetSymbolAddress((void**)&vl,   g_vl);
    cudaGetSymbolAddress((void**)&hTh,  g_hTh);
    cudaGetSymbolAddress((void**)&hTl,  g_hTl);

    const int SM_GEMM = 49152 + 1024;           // 48K tiles, 3 CTAs/SM
    const int SM_ATTN = 2 * 32768 + 1024;       // 66560 -> 3 CTAs/SM
    cudaFuncSetAttribute(mma_gemm<0>, cudaFuncAttributeMaxDynamicSharedMemorySize, SM_GEMM);
    cudaFuncSetAttribute(mma_gemm<3>, cudaFuncAttributeMaxDynamicSharedMemorySize, SM_GEMM);
    cudaFuncSetAttribute(attn_kernel, cudaFuncAttributeMaxDynamicSharedMemorySize, SM_ATTN);

    // 0) weight pre-split
    wsplit_kernel<<<1024, 256>>>(w_qkv, w_proj);

    // 1) GroupNorm + transpose -> xnT hi/lo halves
    gn_stats_kernel<<<Bn * NG, 256>>>(x);
    gn_apply_T_kernel<<<dim3(32, 16, 8), dim3(32, 8)>>>(x, gamma, beta);

    // 2) QKV GEMM (pure half cp.async, 3 CTAs/SM) -> q/k/v hi/lo
    mma_gemm<0><<<dim3(16, 12, 8), 128, SM_GEMM>>>(
        wqh, wql, 512, xnTh, xnTl, 512, 524288, 512, b_qkv, nullptr,
        nullptr, qh, ql, kh, kl, vh, vl);

    // 3) fused flash attention (Q in regs, 3 CTAs/SM) -> hT hi/lo
    attn_kernel<<<dim3(16, 64), 128, SM_ATTN>>>(qh, ql, kh, kl, vh, vl, hTh, hTl);

    // 4) proj GEMM + bias + residual -> out
    mma_gemm<3><<<dim3(16, 4, 8), 128, SM_GEMM>>>(
        wph, wpl, 512, hTh, hTl, 512, 524288, 512, b_proj, x,
        out, nullptr, nullptr, nullptr, nullptr, nullptr, nullptr);
}